// round 12
// baseline (speedup 1.0000x reference)
#include <cuda_runtime.h>
#include <cuda_fp16.h>
#include <stdint.h>
#include <math.h>

// ---------------- problem constants ----------------
#define Bq 2
#define Tq 2048
#define Eq 512
#define Hq 8
#define BT (Bq*Tq)          // 4096
#define HE (Hq*Eq)          // 4096
#define SCALE_F 0.04419417382415922f   // 1/sqrt(512)

static constexpr size_t NTOK   = (size_t)BT * HE;            // 16.7M
static constexpr size_t NSCORE = (size_t)Bq * Hq * Tq * Tq;  // 67.1M
static constexpr size_t NX     = (size_t)BT * Eq;            // 2.1M

// ---------------- scratch (static device memory; no cudaMalloc) ----------------
__device__ float  g_S [NSCORE];
__device__ __half g_Qh[NTOK],  g_Ql[NTOK];
__device__ __half g_Kh[NTOK],  g_Kl[NTOK];
__device__ __half g_Vh[NTOK],  g_Vl[NTOK];
__device__ __half g_Vth[NTOK], g_Vtl[NTOK];     // V transposed: [b][he][t]
__device__ __half g_Oh[NTOK],  g_Ol[NTOK];
__device__ __half g_Ph[NSCORE], g_Pl[NSCORE];
__device__ __half g_xh[NX],   g_xl[NX];
__device__ __half g_Wqh[NX],  g_Wql[NX];
__device__ __half g_Wkh[NX],  g_Wkl[NX];
__device__ __half g_Wvh[NX],  g_Wvl[NX];
__device__ __half g_Wch[NX],  g_Wcl[NX];

// ---------------- PTX helpers (sm_80-level; no tcgen05) ----------------
__device__ __forceinline__ uint32_t smem_u32(const void* p) {
    uint32_t a;
    asm("{ .reg .u64 t; cvta.to.shared.u64 t, %1; cvt.u32.u64 %0, t; }" : "=r"(a) : "l"(p));
    return a;
}
__device__ __forceinline__ void cp16(uint32_t d, const void* s) {
    asm volatile("cp.async.cg.shared.global [%0], [%1], 16;" :: "r"(d), "l"(s) : "memory");
}
__device__ __forceinline__ void cp_commit() {
    asm volatile("cp.async.commit_group;" ::: "memory");
}
template<int N> __device__ __forceinline__ void cp_wait() {
    asm volatile("cp.async.wait_group %0;" :: "n"(N) : "memory");
}
// SW64 swizzle for 64-byte rows: XOR bits[4:6) with bits[7:9)
#define SWZ64(o) ((uint32_t)(o) ^ ((((uint32_t)(o)) >> 3) & 0x30u))

#define LDSM4(r, a) \
    asm volatile("ldmatrix.sync.aligned.m8n8.x4.shared.b16 {%0,%1,%2,%3}, [%4];" \
        : "=r"((r)[0]), "=r"((r)[1]), "=r"((r)[2]), "=r"((r)[3]) : "r"(a))

#define MMA16816(c, a, b) \
    asm volatile("mma.sync.aligned.m16n8k16.row.col.f32.f16.f16.f32 " \
        "{%0,%1,%2,%3}, {%4,%5,%6,%7}, {%8,%9}, {%0,%1,%2,%3};" \
        : "+f"((c)[0]), "+f"((c)[1]), "+f"((c)[2]), "+f"((c)[3]) \
        : "r"((a)[0]), "r"((a)[1]), "r"((a)[2]), "r"((a)[3]), \
          "r"((b)[0]), "r"((b)[1]))

__device__ __forceinline__ uint32_t pkh(__half a, __half b) {
    __half2 h = __halves2half2(a, b);
    return *(uint32_t*)&h;
}

// ---------------- HMMA GEMM: C[M,N] = (Ah+Al)[M,K] @ (Bh+Bl)[N,K]^T ----------------
// CTA tile 128x256, BK=32, 256 threads (8 warps as 2x4, 64x64 warp tiles),
// 4-stage cp.async, single __syncthreads per chunk. Split: AhBh + AhBl + AlBh.
// EPI: 0 = write split fp16 (Ch,Cl); 1 = fp32 * scale; 2 = fp32 + bias[n].
// CSKIP: skip tiles with 2*bn > bm. CK: bound K at (bm+1)*TM.
#define TM 128
#define TN 256
#define TKC 32
// stage layout: Ah 8K | Al 8K | Bh 16K | Bl 16K
#define STAGE_B 49152
#define NSTAGE 4
#define SMEM_REQ (NSTAGE * STAGE_B)   // 192 KB

template<int EPI, bool CSKIP, bool CK>
__global__ __launch_bounds__(256, 1) void tc_gemm(
    const __half* __restrict__ Ahg, const __half* __restrict__ Alg, int lda,
    const __half* __restrict__ Bhg, const __half* __restrict__ Blg, int ldb,
    float* __restrict__ Cf, __half* __restrict__ Chg, __half* __restrict__ Clg,
    int ldc, int K, float scale, const float* __restrict__ bias, int HZ,
    long long sAb, long long sAh_, long long sBb, long long sBh_,
    long long sCb, long long sCh_)
{
    const int bm = blockIdx.y, bn = blockIdx.x;
    if (CSKIP && 2 * bn > bm) return;
    {
        const int z = blockIdx.z, zb = z / HZ, zh = z % HZ;
        const long long ao = zb * sAb + zh * sAh_;
        const long long bo = zb * sBb + zh * sBh_;
        const long long co = zb * sCb + zh * sCh_;
        Ahg += ao; Alg += ao; Bhg += bo; Blg += bo;
        if (Cf)  Cf  += co;
        if (Chg) { Chg += co; Clg += co; }
    }
    int kmax = K;
    if (CK) { int lim = (bm + 1) * TM; kmax = lim < K ? lim : K; }

    extern __shared__ char sm[];
    const uint32_t sbase = smem_u32(sm);

    const int tid  = threadIdx.x;
    const int wid  = tid >> 5;
    const int lane = tid & 31;
    const int m0 = bm * TM, n0 = bn * TN;

    // warp grid: 2 (M) x 4 (N); warp tile 64x64
    const int wm = (wid >> 2) * 64;
    const int wn = (wid & 3) * 64;

    const int a_row = wm + (lane & 15);
    const int a_kb  = (lane >> 4) * 16;
    const int quad  = lane >> 3, qr = lane & 7;
    const int b_row = wn + ((quad >> 1) * 8) + qr;   // + p*16, p in 0..3
    const int b_kb  = (quad & 1) * 16;

    float acc[4][8][4];
    #pragma unroll
    for (int i = 0; i < 4; ++i)
        #pragma unroll
        for (int n = 0; n < 8; ++n)
            #pragma unroll
            for (int r = 0; r < 4; ++r) acc[i][n][r] = 0.f;

    const int nch = kmax / TKC;   // >= 4 always

    auto load_stage = [&](int c, int st) {
        const uint32_t sb = sbase + st * STAGE_B;
        const int k0 = c * TKC;
        // A: 128 rows x 64B per dtype (512 cp16 each)
        #pragma unroll
        for (int it = 0; it < 2; ++it) {
            const int idx = tid + it * 256;          // 0..511
            const int row = idx >> 2, cc = idx & 3;
            const uint32_t so = SWZ64(row * 64 + cc * 16);
            const long long ga = (long long)(m0 + row) * lda + k0 + cc * 8;
            cp16(sb + so,        Ahg + ga);
            cp16(sb + 8192 + so, Alg + ga);
        }
        // B: 256 rows x 64B per dtype (1024 cp16 each)
        #pragma unroll
        for (int it = 0; it < 4; ++it) {
            const int idx = tid + it * 256;          // 0..1023
            const int row = idx >> 2, cc = idx & 3;
            const uint32_t so = SWZ64(row * 64 + cc * 16);
            const long long gb = (long long)(n0 + row) * ldb + k0 + cc * 8;
            cp16(sb + 16384 + so, Bhg + gb);
            cp16(sb + 32768 + so, Blg + gb);
        }
    };

    // prologue: 3 stages in flight
    #pragma unroll
    for (int s = 0; s < 3; ++s) {
        if (s < nch) load_stage(s, s);
        cp_commit();
    }

    for (int c = 0; c < nch; ++c) {
        cp_wait<2>();
        __syncthreads();       // publishes stage c, retires stage c-1

        if (c + 3 < nch) load_stage(c + 3, (c + 3) & 3);
        cp_commit();

        const uint32_t sA_h = sbase + (c & 3) * STAGE_B;
        const uint32_t sA_l = sA_h + 8192;
        const uint32_t sB_h = sA_h + 16384;
        const uint32_t sB_l = sA_h + 32768;

        #pragma unroll
        for (int ks = 0; ks < 2; ++ks) {
            uint32_t ah[4][4], al[4][4];
            #pragma unroll
            for (int i = 0; i < 4; ++i) {
                const uint32_t o = SWZ64((a_row + i * 16) * 64 + ks * 32 + a_kb);
                LDSM4(ah[i], sA_h + o);
                LDSM4(al[i], sA_l + o);
            }
            #pragma unroll
            for (int p = 0; p < 4; ++p) {            // 2 n-atoms per group
                const uint32_t o = SWZ64((b_row + p * 16) * 64 + ks * 32 + b_kb);
                uint32_t rh[4], rl[4];
                LDSM4(rh, sB_h + o);
                LDSM4(rl, sB_l + o);
                #pragma unroll
                for (int na = 0; na < 2; ++na) {
                    uint32_t bh2[2] = { rh[na * 2], rh[na * 2 + 1] };
                    uint32_t bl2[2] = { rl[na * 2], rl[na * 2 + 1] };
                    const int n = p * 2 + na;
                    #pragma unroll
                    for (int i = 0; i < 4; ++i) {
                        MMA16816(acc[i][n], ah[i], bh2);
                        MMA16816(acc[i][n], ah[i], bl2);
                        MMA16816(acc[i][n], al[i], bh2);
                    }
                }
            }
        }
    }

    // ---- epilogue (registers only) ----
    const int gid = lane >> 2, l4 = lane & 3;
    #pragma unroll
    for (int i = 0; i < 4; ++i) {
        const int r0 = m0 + wm + i * 16 + gid;
        #pragma unroll
        for (int n = 0; n < 8; ++n) {
            const int col = n0 + wn + n * 8 + l4 * 2;
            if (EPI == 0) {
                #pragma unroll
                for (int half = 0; half < 2; ++half) {
                    const int rr = r0 + half * 8;
                    const float v0 = acc[i][n][half * 2 + 0];
                    const float v1 = acc[i][n][half * 2 + 1];
                    const __half h0 = __float2half_rn(v0);
                    const __half h1 = __float2half_rn(v1);
                    const __half l0 = __float2half_rn(v0 - __half2float(h0));
                    const __half l1 = __float2half_rn(v1 - __half2float(h1));
                    *(uint32_t*)(Chg + (long long)rr * ldc + col) = pkh(h0, h1);
                    *(uint32_t*)(Clg + (long long)rr * ldc + col) = pkh(l0, l1);
                }
            } else {
                #pragma unroll
                for (int half = 0; half < 2; ++half) {
                    const int rr = r0 + half * 8;
                    float2 v;
                    v.x = acc[i][n][half * 2 + 0];
                    v.y = acc[i][n][half * 2 + 1];
                    if (EPI == 1) { v.x *= scale; v.y *= scale; }
                    if (EPI == 2) { v.x += bias[col]; v.y += bias[col + 1]; }
                    *(float2*)(Cf + (long long)rr * ldc + col) = v;
                }
            }
        }
    }
}

// ---------------- split fp32 -> fp16 hi/lo (vectorized x4) ----------------
__global__ __launch_bounds__(256) void split_kernel(
    const float* __restrict__ in, __half* __restrict__ hi,
    __half* __restrict__ lo, int n4)
{
    const int i = blockIdx.x * 256 + threadIdx.x;
    if (i < n4) {
        const float4 v = ((const float4*)in)[i];
        const __half h0 = __float2half_rn(v.x), h1 = __float2half_rn(v.y);
        const __half h2 = __float2half_rn(v.z), h3 = __float2half_rn(v.w);
        const __half l0 = __float2half_rn(v.x - __half2float(h0));
        const __half l1 = __float2half_rn(v.y - __half2float(h1));
        const __half l2 = __float2half_rn(v.z - __half2float(h2));
        const __half l3 = __float2half_rn(v.w - __half2float(h3));
        uint2 hv; hv.x = pkh(h0, h1); hv.y = pkh(h2, h3);
        uint2 lv; lv.x = pkh(l0, l1); lv.y = pkh(l2, l3);
        ((uint2*)hi)[i] = hv;
        ((uint2*)lo)[i] = lv;
    }
}

// ---------------- tiled transpose of split V: [b, t, he] -> [b, he, t] ----------------
__global__ __launch_bounds__(256) void transpose_kernel(
    const __half* __restrict__ ih, const __half* __restrict__ il,
    __half* __restrict__ oh, __half* __restrict__ ol)
{
    __shared__ __half th[32][33], tl[32][33];
    const int b = blockIdx.z;
    const int n0 = blockIdx.x * 32, t0 = blockIdx.y * 32;
    const int tx = threadIdx.x, ty = threadIdx.y;
    #pragma unroll
    for (int j = ty; j < 32; j += 8) {
        const long long g = ((long long)b * Tq + t0 + j) * HE + n0 + tx;
        th[j][tx] = ih[g];
        tl[j][tx] = il[g];
    }
    __syncthreads();
    #pragma unroll
    for (int j = ty; j < 32; j += 8) {
        const long long g = ((long long)b * HE + n0 + j) * Tq + t0 + tx;
        oh[g] = th[tx][j];
        ol[g] = tl[tx][j];
    }
}

// ---------------- causal softmax: single gmem read, fp32 -> split fp16 ----------------
__global__ __launch_bounds__(256) void softmax_kernel(
    const float* __restrict__ S, __half* __restrict__ Ph,
    __half* __restrict__ Pl)
{
    const int z = blockIdx.y, q = blockIdx.x;
    const long long base = (long long)z * Tq * Tq + (long long)q * Tq;
    const float* row = S + base;
    __half* ph_ = Ph + base;
    __half* pl_ = Pl + base;
    const int len = q + 1;
    const int klim = ((q >> 7) + 1) << 7;   // PV reads only k < klim
    const int tid = threadIdx.x;

    __shared__ float rowbuf[Tq];
    __shared__ float red[256];

    float m = -1e30f;
    for (int k = tid; k < len; k += 256) {
        const float v = row[k];
        rowbuf[k] = v;
        m = fmaxf(m, v);
    }
    red[tid] = m; __syncthreads();
    for (int s = 128; s > 0; s >>= 1) {
        if (tid < s) red[tid] = fmaxf(red[tid], red[tid + s]);
        __syncthreads();
    }
    m = red[0]; __syncthreads();

    float sum = 0.f;
    for (int k = tid; k < len; k += 256) {
        const float e = expf(rowbuf[k] - m);
        rowbuf[k] = e;
        sum += e;
    }
    red[tid] = sum; __syncthreads();
    for (int s = 128; s > 0; s >>= 1) {
        if (tid < s) red[tid] += red[tid + s];
        __syncthreads();
    }
    const float inv = 1.0f / red[0]; __syncthreads();

    for (int k = tid; k < klim; k += 256) {
        const float p = (k < len) ? rowbuf[k] * inv : 0.0f;
        const __half h = __float2half_rn(p);
        ph_[k] = h;
        pl_[k] = __float2half_rn(p - __half2float(h));
    }
}

// ---------------- host ----------------
extern "C" void kernel_launch(void* const* d_in, const int* in_sizes, int n_in,
                              void* d_out, int out_size)
{
    const float* x  = (const float*)d_in[0];
    const float* Wk = (const float*)d_in[1];
    const float* Wq = (const float*)d_in[2];
    const float* Wv = (const float*)d_in[3];
    const float* Wc = (const float*)d_in[4];
    const float* bc = (const float*)d_in[5];
    float* out = (float*)d_out;

    float* S;
    __half *Qh, *Ql, *Kh, *Kl, *Vh, *Vl, *Vth, *Vtl, *Oh, *Ol, *Ph, *Pl;
    __half *xh, *xl, *Wqh, *Wql, *Wkh, *Wkl, *Wvh, *Wvl, *Wch, *Wcl;
    cudaGetSymbolAddress((void**)&S,   g_S);
    cudaGetSymbolAddress((void**)&Qh,  g_Qh);  cudaGetSymbolAddress((void**)&Ql,  g_Ql);
    cudaGetSymbolAddress((void**)&Kh,  g_Kh);  cudaGetSymbolAddress((void**)&Kl,  g_Kl);
    cudaGetSymbolAddress((void**)&Vh,  g_Vh);  cudaGetSymbolAddress((void**)&Vl,  g_Vl);
    cudaGetSymbolAddress((void**)&Vth, g_Vth); cudaGetSymbolAddress((void**)&Vtl, g_Vtl);
    cudaGetSymbolAddress((void**)&Oh,  g_Oh);  cudaGetSymbolAddress((void**)&Ol,  g_Ol);
    cudaGetSymbolAddress((void**)&Ph,  g_Ph);  cudaGetSymbolAddress((void**)&Pl,  g_Pl);
    cudaGetSymbolAddress((void**)&xh,  g_xh);  cudaGetSymbolAddress((void**)&xl,  g_xl);
    cudaGetSymbolAddress((void**)&Wqh, g_Wqh); cudaGetSymbolAddress((void**)&Wql, g_Wql);
    cudaGetSymbolAddress((void**)&Wkh, g_Wkh); cudaGetSymbolAddress((void**)&Wkl, g_Wkl);
    cudaGetSymbolAddress((void**)&Wvh, g_Wvh); cudaGetSymbolAddress((void**)&Wvl, g_Wvl);
    cudaGetSymbolAddress((void**)&Wch, g_Wch); cudaGetSymbolAddress((void**)&Wcl, g_Wcl);

    cudaFuncSetAttribute(tc_gemm<0, false, false>, cudaFuncAttributeMaxDynamicSharedMemorySize, SMEM_REQ);
    cudaFuncSetAttribute(tc_gemm<1, true,  false>, cudaFuncAttributeMaxDynamicSharedMemorySize, SMEM_REQ);
    cudaFuncSetAttribute(tc_gemm<0, false, true >, cudaFuncAttributeMaxDynamicSharedMemorySize, SMEM_REQ);
    cudaFuncSetAttribute(tc_gemm<2, false, false>, cudaFuncAttributeMaxDynamicSharedMemorySize, SMEM_REQ);

    const dim3 blk(256);

    // 0) split inputs (vectorized x4)
    {
        const int n4 = (int)(NX / 4);
        const int g = (n4 + 255) / 256;
        split_kernel<<<g, 256>>>(x,  xh,  xl,  n4);
        split_kernel<<<g, 256>>>(Wq, Wqh, Wql, n4);
        split_kernel<<<g, 256>>>(Wk, Wkh, Wkl, n4);
        split_kernel<<<g, 256>>>(Wv, Wvh, Wvl, n4);
        split_kernel<<<g, 256>>>(Wc, Wch, Wcl, n4);
    }

    // 1) projections: [BT, HE] = x[BT, Eq] @ W[HE, Eq]^T (split outputs)
    {
        dim3 grid(HE / TN, BT / TM, 1);
        tc_gemm<0, false, false><<<grid, blk, SMEM_REQ>>>(
            xh, xl, Eq, Wqh, Wql, Eq, nullptr, Qh, Ql, HE,
            Eq, 0.f, nullptr, 1, 0, 0, 0, 0, 0, 0);
        tc_gemm<0, false, false><<<grid, blk, SMEM_REQ>>>(
            xh, xl, Eq, Wkh, Wkl, Eq, nullptr, Kh, Kl, HE,
            Eq, 0.f, nullptr, 1, 0, 0, 0, 0, 0, 0);
        tc_gemm<0, false, false><<<grid, blk, SMEM_REQ>>>(
            xh, xl, Eq, Wvh, Wvl, Eq, nullptr, Vh, Vl, HE,
            Eq, 0.f, nullptr, 1, 0, 0, 0, 0, 0, 0);
    }

    // 2) transpose V -> [b, he, t] (K-major B for PV)
    {
        dim3 grid(HE / 32, Tq / 32, Bq), b2(32, 8);
        transpose_kernel<<<grid, b2>>>(Vh, Vl, Vth, Vtl);
    }

    // 3) scores: S = scale * Q K^T (causal tile skip, fp32 out)
    {
        dim3 grid(Tq / TN, Tq / TM, Bq * Hq);
        tc_gemm<1, true, false><<<grid, blk, SMEM_REQ>>>(
            Qh, Ql, HE, Kh, Kl, HE, S, nullptr, nullptr, Tq,
            Eq, SCALE_F, nullptr, Hq,
            (long long)Tq * HE, (long long)Eq,
            (long long)Tq * HE, (long long)Eq,
            (long long)Hq * Tq * Tq, (long long)Tq * Tq);
    }

    // 4) softmax -> split probs
    {
        dim3 grid(Tq, Bq * Hq);
        softmax_kernel<<<grid, 256>>>(S, Ph, Pl);
    }

    // 5) PV: O = P @ V (causal K bound, split output)
    {
        dim3 grid(Eq / TN, Tq / TM, Bq * Hq);
        tc_gemm<0, false, true><<<grid, blk, SMEM_REQ>>>(
            Ph, Pl, Tq, Vth, Vtl, Tq, nullptr, Oh, Ol, HE,
            Tq, 0.f, nullptr, Hq,
            (long long)Hq * Tq * Tq, (long long)Tq * Tq,
            (long long)HE * Tq, (long long)Eq * Tq,
            (long long)Tq * HE, (long long)Eq);
    }

    // 6) output projection: out = O @ Wc^T + bc (fp32)
    {
        dim3 grid(Eq / TN, BT / TM, 1);
        tc_gemm<2, false, false><<<grid, blk, SMEM_REQ>>>(
            Oh, Ol, HE, Wch, Wcl, HE, out, nullptr, nullptr, Eq,
            HE, 0.f, bc, 1, 0, 0, 0, 0, 0, 0);
    }
}

// round 15
// speedup vs baseline: 1.2533x; 1.2533x over previous
#include <cuda_runtime.h>
#include <cuda_fp16.h>
#include <stdint.h>
#include <math.h>

// ---------------- problem constants ----------------
#define Bq 2
#define Tq 2048
#define Eq 512
#define Hq 8
#define BT (Bq*Tq)          // 4096
#define HE (Hq*Eq)          // 4096
#define SCALE_F 0.04419417382415922f   // 1/sqrt(512)

static constexpr size_t NTOK   = (size_t)BT * HE;            // 16.7M
static constexpr size_t NSCORE = (size_t)Bq * Hq * Tq * Tq;  // 67.1M
static constexpr size_t NX     = (size_t)BT * Eq;            // 2.1M

// ---------------- scratch (static device memory; no cudaMalloc) ----------------
__device__ float  g_S [NSCORE];
__device__ __half g_Qh[NTOK],  g_Ql[NTOK];
__device__ __half g_Kh[NTOK],  g_Kl[NTOK];
__device__ __half g_Vh[NTOK],  g_Vl[NTOK];
__device__ __half g_Vth[NTOK], g_Vtl[NTOK];     // V transposed: [b][he][t]
__device__ __half g_Oh[NTOK];                    // O plain fp16 (post-softmax)
__device__ __half g_Ph[NSCORE];                  // probs plain fp16 (post-softmax)
__device__ __half g_xh[NX],   g_xl[NX];
__device__ __half g_Wqh[NX],  g_Wql[NX];
__device__ __half g_Wkh[NX],  g_Wkl[NX];
__device__ __half g_Wvh[NX],  g_Wvl[NX];
__device__ __half g_Wch[NX],  g_Wcl[NX];

// ---------------- PTX helpers (sm_80-level; no tcgen05) ----------------
__device__ __forceinline__ uint32_t smem_u32(const void* p) {
    uint32_t a;
    asm("{ .reg .u64 t; cvta.to.shared.u64 t, %1; cvt.u32.u64 %0, t; }" : "=r"(a) : "l"(p));
    return a;
}
__device__ __forceinline__ void cp16(uint32_t d, const void* s) {
    asm volatile("cp.async.cg.shared.global [%0], [%1], 16;" :: "r"(d), "l"(s) : "memory");
}
__device__ __forceinline__ void cp_commit() {
    asm volatile("cp.async.commit_group;" ::: "memory");
}
template<int N> __device__ __forceinline__ void cp_wait() {
    asm volatile("cp.async.wait_group %0;" :: "n"(N) : "memory");
}
// SW64 swizzle for 64-byte rows: XOR bits[4:6) with bits[7:9)
#define SWZ64(o) ((uint32_t)(o) ^ ((((uint32_t)(o)) >> 3) & 0x30u))

#define LDSM4(r, a) \
    asm volatile("ldmatrix.sync.aligned.m8n8.x4.shared.b16 {%0,%1,%2,%3}, [%4];" \
        : "=r"((r)[0]), "=r"((r)[1]), "=r"((r)[2]), "=r"((r)[3]) : "r"(a))

#define MMA16816(c, a, b) \
    asm volatile("mma.sync.aligned.m16n8k16.row.col.f32.f16.f16.f32 " \
        "{%0,%1,%2,%3}, {%4,%5,%6,%7}, {%8,%9}, {%0,%1,%2,%3};" \
        : "+f"((c)[0]), "+f"((c)[1]), "+f"((c)[2]), "+f"((c)[3]) \
        : "r"((a)[0]), "r"((a)[1]), "r"((a)[2]), "r"((a)[3]), \
          "r"((b)[0]), "r"((b)[1]))

__device__ __forceinline__ uint32_t pkh(__half a, __half b) {
    __half2 h = __halves2half2(a, b);
    return *(uint32_t*)&h;
}

// ---------------- HMMA GEMM ----------------
// C[M,N] = A[M,K] @ (Bh+Bl)[N,K]^T, with A = (Ah+Al) split (ASPLIT) or plain fp16.
// CTA 128x128, BK=32, 256 threads (8 warps, 64x32 warp tiles), 4-stage cp.async,
// one __syncthreads per chunk.
// ASPLIT: MMAs AhBh + AhBl + AlBh (3). !ASPLIT: A Bh + A Bl (2), smaller stage.
// EPI: 0 = split fp16 (Ch,Cl); 1 = fp32*scale; 2 = fp32+bias; 3 = plain fp16 (Ch).
// CSKIP: skip tiles with bn > bm. CK: bound K at (bm+1)*TM, reversed bm order.
#define TM 128
#define TN 128
#define TKC 32

template<int EPI, bool CSKIP, bool CK, bool ASPLIT>
__global__ __launch_bounds__(256, ASPLIT ? 1 : 2) void tc_gemm(
    const __half* __restrict__ Ahg, const __half* __restrict__ Alg, int lda,
    const __half* __restrict__ Bhg, const __half* __restrict__ Blg, int ldb,
    float* __restrict__ Cf, __half* __restrict__ Chg, __half* __restrict__ Clg,
    int ldc, int K, float scale, const float* __restrict__ bias, int HZ,
    long long sAb, long long sAh_, long long sBb, long long sBh_,
    long long sCb, long long sCh_)
{
    constexpr uint32_t STB    = ASPLIT ? 32768u : 24576u;  // stage bytes
    constexpr uint32_t OFF_AL = 8192u;                     // (ASPLIT only)
    constexpr uint32_t OFF_BH = ASPLIT ? 16384u : 8192u;
    constexpr uint32_t OFF_BL = ASPLIT ? 24576u : 16384u;

    const int bm = CK ? (int)(gridDim.y - 1 - blockIdx.y) : (int)blockIdx.y;
    const int bn = blockIdx.x;
    if (CSKIP && bn > bm) return;
    {
        const int z = blockIdx.z, zb = z / HZ, zh = z % HZ;
        const long long ao = zb * sAb + zh * sAh_;
        const long long bo = zb * sBb + zh * sBh_;
        const long long co = zb * sCb + zh * sCh_;
        Ahg += ao; if (ASPLIT) Alg += ao;
        Bhg += bo; Blg += bo;
        if (Cf)  Cf  += co;
        if (Chg) Chg += co;
        if (Clg) Clg += co;
    }
    int kmax = K;
    if (CK) { int lim = (bm + 1) * TM; kmax = lim < K ? lim : K; }

    extern __shared__ char sm[];
    const uint32_t sbase = smem_u32(sm);

    const int tid  = threadIdx.x;
    const int wid  = tid >> 5;
    const int lane = tid & 31;
    const int m0 = bm * TM, n0 = bn * TN;

    // warp tile: 64x32 (wm in {0,64}, wn in {0,32,64,96})
    const int wm = (wid >> 2) * 64;
    const int wn = (wid & 3) * 32;

    const int a_row = wm + (lane & 15);
    const int a_kb  = (lane >> 4) * 16;
    const int quad  = lane >> 3, qr = lane & 7;
    const int b_row = wn + ((quad >> 1) * 8) + qr;
    const int b_kb  = (quad & 1) * 16;

    float acc[4][4][4];
    #pragma unroll
    for (int i = 0; i < 4; ++i)
        #pragma unroll
        for (int n = 0; n < 4; ++n)
            #pragma unroll
            for (int r = 0; r < 4; ++r) acc[i][n][r] = 0.f;

    const int nch = kmax / TKC;   // >= 4 always

    auto load_stage = [&](int c, int st) {
        const uint32_t sb = sbase + st * STB;
        const int k0 = c * TKC;
        #pragma unroll
        for (int it = 0; it < 2; ++it) {
            const int idx = tid + it * 256;      // 0..511
            const int row = idx >> 2, cc = idx & 3;
            const uint32_t so = SWZ64(row * 64 + cc * 16);
            const long long ga = (long long)(m0 + row) * lda + k0 + cc * 8;
            cp16(sb + so, Ahg + ga);
            if (ASPLIT) cp16(sb + OFF_AL + so, Alg + ga);
            const long long gb = (long long)(n0 + row) * ldb + k0 + cc * 8;
            cp16(sb + OFF_BH + so, Bhg + gb);
            cp16(sb + OFF_BL + so, Blg + gb);
        }
    };

    // prologue: 3 stages in flight
    #pragma unroll
    for (int s = 0; s < 3; ++s) {
        if (s < nch) load_stage(s, s);
        cp_commit();
    }

    for (int c = 0; c < nch; ++c) {
        cp_wait<2>();
        __syncthreads();       // publishes stage c, retires stage c-1

        if (c + 3 < nch) load_stage(c + 3, (c + 3) & 3);
        cp_commit();

        const uint32_t sA_h = sbase + (c & 3) * STB;
        const uint32_t sA_l = sA_h + OFF_AL;
        const uint32_t sB_h = sA_h + OFF_BH;
        const uint32_t sB_l = sA_h + OFF_BL;

        #pragma unroll
        for (int ks = 0; ks < 2; ++ks) {
            uint32_t ah[4][4], al[4][4], bh[4][2], bl[4][2];
            #pragma unroll
            for (int i = 0; i < 4; ++i) {
                const uint32_t o = SWZ64((a_row + i * 16) * 64 + ks * 32 + a_kb);
                LDSM4(ah[i], sA_h + o);
                if (ASPLIT) LDSM4(al[i], sA_l + o);
            }
            #pragma unroll
            for (int p = 0; p < 2; ++p) {
                const uint32_t o = SWZ64((b_row + p * 16) * 64 + ks * 32 + b_kb);
                uint32_t r[4];
                LDSM4(r, sB_h + o);
                bh[p*2][0] = r[0]; bh[p*2][1] = r[1];
                bh[p*2+1][0] = r[2]; bh[p*2+1][1] = r[3];
                LDSM4(r, sB_l + o);
                bl[p*2][0] = r[0]; bl[p*2][1] = r[1];
                bl[p*2+1][0] = r[2]; bl[p*2+1][1] = r[3];
            }
            #pragma unroll
            for (int i = 0; i < 4; ++i)
                #pragma unroll
                for (int n = 0; n < 4; ++n) {
                    MMA16816(acc[i][n], ah[i], bh[n]);
                    MMA16816(acc[i][n], ah[i], bl[n]);
                    if (ASPLIT) MMA16816(acc[i][n], al[i], bh[n]);
                }
        }
    }

    // ---- epilogue (registers only) ----
    const int gid = lane >> 2, l4 = lane & 3;
    #pragma unroll
    for (int i = 0; i < 4; ++i) {
        const int r0 = m0 + wm + i * 16 + gid;
        #pragma unroll
        for (int n = 0; n < 4; ++n) {
            const int col = n0 + wn + n * 8 + l4 * 2;
            if (EPI == 0) {
                #pragma unroll
                for (int half = 0; half < 2; ++half) {
                    const int rr = r0 + half * 8;
                    const float v0 = acc[i][n][half * 2 + 0];
                    const float v1 = acc[i][n][half * 2 + 1];
                    const __half h0 = __float2half_rn(v0);
                    const __half h1 = __float2half_rn(v1);
                    const __half l0 = __float2half_rn(v0 - __half2float(h0));
                    const __half l1 = __float2half_rn(v1 - __half2float(h1));
                    *(uint32_t*)(Chg + (long long)rr * ldc + col) = pkh(h0, h1);
                    *(uint32_t*)(Clg + (long long)rr * ldc + col) = pkh(l0, l1);
                }
            } else if (EPI == 3) {
                #pragma unroll
                for (int half = 0; half < 2; ++half) {
                    const int rr = r0 + half * 8;
                    const __half h0 = __float2half_rn(acc[i][n][half * 2 + 0]);
                    const __half h1 = __float2half_rn(acc[i][n][half * 2 + 1]);
                    *(uint32_t*)(Chg + (long long)rr * ldc + col) = pkh(h0, h1);
                }
            } else {
                #pragma unroll
                for (int half = 0; half < 2; ++half) {
                    const int rr = r0 + half * 8;
                    float2 v;
                    v.x = acc[i][n][half * 2 + 0];
                    v.y = acc[i][n][half * 2 + 1];
                    if (EPI == 1) { v.x *= scale; v.y *= scale; }
                    if (EPI == 2) { v.x += bias[col]; v.y += bias[col + 1]; }
                    *(float2*)(Cf + (long long)rr * ldc + col) = v;
                }
            }
        }
    }
}

// ---------------- split fp32 -> fp16 hi/lo (vectorized x4) ----------------
__global__ __launch_bounds__(256) void split_kernel(
    const float* __restrict__ in, __half* __restrict__ hi,
    __half* __restrict__ lo, int n4)
{
    const int i = blockIdx.x * 256 + threadIdx.x;
    if (i < n4) {
        const float4 v = ((const float4*)in)[i];
        const __half h0 = __float2half_rn(v.x), h1 = __float2half_rn(v.y);
        const __half h2 = __float2half_rn(v.z), h3 = __float2half_rn(v.w);
        const __half l0 = __float2half_rn(v.x - __half2float(h0));
        const __half l1 = __float2half_rn(v.y - __half2float(h1));
        const __half l2 = __float2half_rn(v.z - __half2float(h2));
        const __half l3 = __float2half_rn(v.w - __half2float(h3));
        uint2 hv; hv.x = pkh(h0, h1); hv.y = pkh(h2, h3);
        uint2 lv; lv.x = pkh(l0, l1); lv.y = pkh(l2, l3);
        ((uint2*)hi)[i] = hv;
        ((uint2*)lo)[i] = lv;
    }
}

// ---------------- tiled transpose of split V: [b, t, he] -> [b, he, t] ----------------
__global__ __launch_bounds__(256) void transpose_kernel(
    const __half* __restrict__ ih, const __half* __restrict__ il,
    __half* __restrict__ oh, __half* __restrict__ ol)
{
    __shared__ __half th[32][33], tl[32][33];
    const int b = blockIdx.z;
    const int n0 = blockIdx.x * 32, t0 = blockIdx.y * 32;
    const int tx = threadIdx.x, ty = threadIdx.y;
    #pragma unroll
    for (int j = ty; j < 32; j += 8) {
        const long long g = ((long long)b * Tq + t0 + j) * HE + n0 + tx;
        th[j][tx] = ih[g];
        tl[j][tx] = il[g];
    }
    __syncthreads();
    #pragma unroll
    for (int j = ty; j < 32; j += 8) {
        const long long g = ((long long)b * HE + n0 + j) * Tq + t0 + tx;
        oh[g] = th[tx][j];
        ol[g] = tl[tx][j];
    }
}

// ---------------- causal softmax: fp32 scores -> plain fp16 probs ----------------
__global__ __launch_bounds__(256) void softmax_kernel(
    const float* __restrict__ S, __half* __restrict__ Ph)
{
    const int z = blockIdx.y, q = blockIdx.x;
    const long long base = (long long)z * Tq * Tq + (long long)q * Tq;
    const float* row = S + base;
    __half* ph_ = Ph + base;
    const int len = q + 1;
    const int klim = ((q >> 7) + 1) << 7;   // PV reads only k < klim
    const int tid = threadIdx.x;

    __shared__ float rowbuf[Tq];
    __shared__ float red[256];

    float m = -1e30f;
    for (int k = tid; k < len; k += 256) {
        const float v = row[k];
        rowbuf[k] = v;
        m = fmaxf(m, v);
    }
    red[tid] = m; __syncthreads();
    for (int s = 128; s > 0; s >>= 1) {
        if (tid < s) red[tid] = fmaxf(red[tid], red[tid + s]);
        __syncthreads();
    }
    m = red[0]; __syncthreads();

    float sum = 0.f;
    for (int k = tid; k < len; k += 256) {
        const float e = expf(rowbuf[k] - m);
        rowbuf[k] = e;
        sum += e;
    }
    red[tid] = sum; __syncthreads();
    for (int s = 128; s > 0; s >>= 1) {
        if (tid < s) red[tid] += red[tid + s];
        __syncthreads();
    }
    const float inv = 1.0f / red[0]; __syncthreads();

    for (int k = tid; k < klim; k += 256) {
        const float p = (k < len) ? rowbuf[k] * inv : 0.0f;
        ph_[k] = __float2half_rn(p);
    }
}

// ---------------- host ----------------
extern "C" void kernel_launch(void* const* d_in, const int* in_sizes, int n_in,
                              void* d_out, int out_size)
{
    const float* x  = (const float*)d_in[0];
    const float* Wk = (const float*)d_in[1];
    const float* Wq = (const float*)d_in[2];
    const float* Wv = (const float*)d_in[3];
    const float* Wc = (const float*)d_in[4];
    const float* bc = (const float*)d_in[5];
    float* out = (float*)d_out;

    float* S;
    __half *Qh, *Ql, *Kh, *Kl, *Vh, *Vl, *Vth, *Vtl, *Oh, *Ph;
    __half *xh, *xl, *Wqh, *Wql, *Wkh, *Wkl, *Wvh, *Wvl, *Wch, *Wcl;
    cudaGetSymbolAddress((void**)&S,   g_S);
    cudaGetSymbolAddress((void**)&Qh,  g_Qh);  cudaGetSymbolAddress((void**)&Ql,  g_Ql);
    cudaGetSymbolAddress((void**)&Kh,  g_Kh);  cudaGetSymbolAddress((void**)&Kl,  g_Kl);
    cudaGetSymbolAddress((void**)&Vh,  g_Vh);  cudaGetSymbolAddress((void**)&Vl,  g_Vl);
    cudaGetSymbolAddress((void**)&Vth, g_Vth); cudaGetSymbolAddress((void**)&Vtl, g_Vtl);
    cudaGetSymbolAddress((void**)&Oh,  g_Oh);
    cudaGetSymbolAddress((void**)&Ph,  g_Ph);
    cudaGetSymbolAddress((void**)&xh,  g_xh);  cudaGetSymbolAddress((void**)&xl,  g_xl);
    cudaGetSymbolAddress((void**)&Wqh, g_Wqh); cudaGetSymbolAddress((void**)&Wql, g_Wql);
    cudaGetSymbolAddress((void**)&Wkh, g_Wkh); cudaGetSymbolAddress((void**)&Wkl, g_Wkl);
    cudaGetSymbolAddress((void**)&Wvh, g_Wvh); cudaGetSymbolAddress((void**)&Wvl, g_Wvl);
    cudaGetSymbolAddress((void**)&Wch, g_Wch); cudaGetSymbolAddress((void**)&Wcl, g_Wcl);

    const int SM_SPLIT  = 4 * 32768;   // ASPLIT stages
    const int SM_SINGLE = 4 * 24576;   // A-single stages

    cudaFuncSetAttribute(tc_gemm<0, false, false, true >, cudaFuncAttributeMaxDynamicSharedMemorySize, SM_SPLIT);
    cudaFuncSetAttribute(tc_gemm<1, true,  false, true >, cudaFuncAttributeMaxDynamicSharedMemorySize, SM_SPLIT);
    cudaFuncSetAttribute(tc_gemm<3, false, true,  false>, cudaFuncAttributeMaxDynamicSharedMemorySize, SM_SINGLE);
    cudaFuncSetAttribute(tc_gemm<2, false, false, false>, cudaFuncAttributeMaxDynamicSharedMemorySize, SM_SINGLE);

    const dim3 blk(256);

    // 0) split inputs (vectorized x4)
    {
        const int n4 = (int)(NX / 4);
        const int g = (n4 + 255) / 256;
        split_kernel<<<g, 256>>>(x,  xh,  xl,  n4);
        split_kernel<<<g, 256>>>(Wq, Wqh, Wql, n4);
        split_kernel<<<g, 256>>>(Wk, Wkh, Wkl, n4);
        split_kernel<<<g, 256>>>(Wv, Wvh, Wvl, n4);
        split_kernel<<<g, 256>>>(Wc, Wch, Wcl, n4);
    }

    // 1) projections: [BT, HE] = x[BT, Eq] @ W[HE, Eq]^T (split outputs, 3-term)
    {
        dim3 grid(HE / TN, BT / TM, 1);
        tc_gemm<0, false, false, true><<<grid, blk, SM_SPLIT>>>(
            xh, xl, Eq, Wqh, Wql, Eq, nullptr, Qh, Ql, HE,
            Eq, 0.f, nullptr, 1, 0, 0, 0, 0, 0, 0);
        tc_gemm<0, false, false, true><<<grid, blk, SM_SPLIT>>>(
            xh, xl, Eq, Wkh, Wkl, Eq, nullptr, Kh, Kl, HE,
            Eq, 0.f, nullptr, 1, 0, 0, 0, 0, 0, 0);
        tc_gemm<0, false, false, true><<<grid, blk, SM_SPLIT>>>(
            xh, xl, Eq, Wvh, Wvl, Eq, nullptr, Vh, Vl, HE,
            Eq, 0.f, nullptr, 1, 0, 0, 0, 0, 0, 0);
    }

    // 2) transpose V -> [b, he, t] (K-major B for PV)
    {
        dim3 grid(HE / 32, Tq / 32, Bq), b2(32, 8);
        transpose_kernel<<<grid, b2>>>(Vh, Vl, Vth, Vtl);
    }

    // 3) scores: S = scale * Q K^T (causal tile skip, 3-term, fp32 out)
    {
        dim3 grid(Tq / TN, Tq / TM, Bq * Hq);
        tc_gemm<1, true, false, true><<<grid, blk, SM_SPLIT>>>(
            Qh, Ql, HE, Kh, Kl, HE, S, nullptr, nullptr, Tq,
            Eq, SCALE_F, nullptr, Hq,
            (long long)Tq * HE, (long long)Eq,
            (long long)Tq * HE, (long long)Eq,
            (long long)Hq * Tq * Tq, (long long)Tq * Tq);
    }

    // 4) softmax -> plain fp16 probs
    {
        dim3 grid(Tq, Bq * Hq);
        softmax_kernel<<<grid, 256>>>(S, Ph);
    }

    // 5) PV: O = P @ V (A single fp16, B split, causal K bound, fp16 out)
    {
        dim3 grid(Eq / TN, Tq / TM, Bq * Hq);
        tc_gemm<3, false, true, false><<<grid, blk, SM_SINGLE>>>(
            Ph, nullptr, Tq, Vth, Vtl, Tq, nullptr, Oh, nullptr, HE,
            Tq, 0.f, nullptr, Hq,
            (long long)Hq * Tq * Tq, (long long)Tq * Tq,
            (long long)HE * Tq, (long long)Eq * Tq,
            (long long)Tq * HE, (long long)Eq);
    }

    // 6) output projection: out = O @ Wc^T + bc (A single fp16, B split, fp32)
    {
        dim3 grid(Eq / TN, BT / TM, 1);
        tc_gemm<2, false, false, false><<<grid, blk, SM_SINGLE>>>(
            Oh, nullptr, HE, Wch, Wcl, HE, out, nullptr, nullptr, Eq,
            HE, 0.f, bc, 1, 0, 0, 0, 0, 0, 0);
    }
}

// round 17
// speedup vs baseline: 1.3235x; 1.0560x over previous
#include <cuda_runtime.h>
#include <cuda_fp16.h>
#include <stdint.h>
#include <math.h>

// ---------------- problem constants ----------------
#define Bq 2
#define Tq 2048
#define Eq 512
#define Hq 8
#define BT (Bq*Tq)          // 4096
#define HE (Hq*Eq)          // 4096
#define SCALE_F 0.04419417382415922f   // 1/sqrt(512)

static constexpr size_t NTOK   = (size_t)BT * HE;            // 16.7M
static constexpr size_t NSCORE = (size_t)Bq * Hq * Tq * Tq;  // 67.1M
static constexpr size_t NX     = (size_t)BT * Eq;            // 2.1M

// ---------------- scratch (static device memory; no cudaMalloc) ----------------
__device__ float  g_S [NSCORE];
__device__ __half g_Qh[NTOK],  g_Ql[NTOK];
__device__ __half g_Kh[NTOK],  g_Kl[NTOK];
__device__ __half g_Vh[NTOK],  g_Vl[NTOK];
__device__ __half g_Vth[NTOK], g_Vtl[NTOK];     // V transposed: [b][he][t]
__device__ __half g_Oh[NTOK];                    // O plain fp16 (post-softmax)
__device__ __half g_Ph[NSCORE];                  // probs plain fp16 (post-softmax)
__device__ __half g_xh[NX],   g_xl[NX];
__device__ __half g_Wqh[NX],  g_Wql[NX];
__device__ __half g_Wkh[NX],  g_Wkl[NX];
__device__ __half g_Wvh[NX],  g_Wvl[NX];
__device__ __half g_Wch[NX],  g_Wcl[NX];

// ---------------- PTX helpers (sm_80-level; no tcgen05) ----------------
__device__ __forceinline__ uint32_t smem_u32(const void* p) {
    uint32_t a;
    asm("{ .reg .u64 t; cvta.to.shared.u64 t, %1; cvt.u32.u64 %0, t; }" : "=r"(a) : "l"(p));
    return a;
}
__device__ __forceinline__ void cp16(uint32_t d, const void* s) {
    asm volatile("cp.async.cg.shared.global [%0], [%1], 16;" :: "r"(d), "l"(s) : "memory");
}
__device__ __forceinline__ void cp_commit() {
    asm volatile("cp.async.commit_group;" ::: "memory");
}
template<int N> __device__ __forceinline__ void cp_wait() {
    asm volatile("cp.async.wait_group %0;" :: "n"(N) : "memory");
}
// SW64 swizzle for 64-byte rows: XOR bits[4:6) with bits[7:9)
#define SWZ64(o) ((uint32_t)(o) ^ ((((uint32_t)(o)) >> 3) & 0x30u))

#define LDSM4(r, a) \
    asm volatile("ldmatrix.sync.aligned.m8n8.x4.shared.b16 {%0,%1,%2,%3}, [%4];" \
        : "=r"((r)[0]), "=r"((r)[1]), "=r"((r)[2]), "=r"((r)[3]) : "r"(a))

#define MMA16816(c, a, b) \
    asm volatile("mma.sync.aligned.m16n8k16.row.col.f32.f16.f16.f32 " \
        "{%0,%1,%2,%3}, {%4,%5,%6,%7}, {%8,%9}, {%0,%1,%2,%3};" \
        : "+f"((c)[0]), "+f"((c)[1]), "+f"((c)[2]), "+f"((c)[3]) \
        : "r"((a)[0]), "r"((a)[1]), "r"((a)[2]), "r"((a)[3]), \
          "r"((b)[0]), "r"((b)[1]))

__device__ __forceinline__ uint32_t pkh(__half a, __half b) {
    __half2 h = __halves2half2(a, b);
    return *(uint32_t*)&h;
}

// ---------------- HMMA GEMM ----------------
// C[M,N] = A[M,K] @ (Bh+Bl)[N,K]^T, with A = (Ah+Al) split (ASPLIT) or plain fp16.
// CTA 128x128, BK=32, 256 threads (8 warps, 64x32 warp tiles), 3-stage cp.async,
// one __syncthreads per chunk, 2 CTAs/SM.
// ASPLIT: MMAs AhBh + AhBl + AlBh (3). !ASPLIT: A Bh + A Bl (2), smaller stage.
// EPI: 0 = split fp16 (Ch,Cl); 1 = fp32*scale; 2 = fp32+bias; 3 = plain fp16 (Ch).
// CSKIP: skip tiles with bn > bm. CK: bound K at (bm+1)*TM, reversed bm order.
#define TM 128
#define TN 128
#define TKC 32

template<int EPI, bool CSKIP, bool CK, bool ASPLIT>
__global__ __launch_bounds__(256, 2) void tc_gemm(
    const __half* __restrict__ Ahg, const __half* __restrict__ Alg, int lda,
    const __half* __restrict__ Bhg, const __half* __restrict__ Blg, int ldb,
    float* __restrict__ Cf, __half* __restrict__ Chg, __half* __restrict__ Clg,
    int ldc, int K, float scale, const float* __restrict__ bias, int HZ,
    long long sAb, long long sAh_, long long sBb, long long sBh_,
    long long sCb, long long sCh_)
{
    constexpr uint32_t STB    = ASPLIT ? 32768u : 24576u;  // stage bytes
    constexpr uint32_t OFF_AL = 8192u;                     // (ASPLIT only)
    constexpr uint32_t OFF_BH = ASPLIT ? 16384u : 8192u;
    constexpr uint32_t OFF_BL = ASPLIT ? 24576u : 16384u;

    const int bm = CK ? (int)(gridDim.y - 1 - blockIdx.y) : (int)blockIdx.y;
    const int bn = blockIdx.x;
    if (CSKIP && bn > bm) return;
    {
        const int z = blockIdx.z, zb = z / HZ, zh = z % HZ;
        const long long ao = zb * sAb + zh * sAh_;
        const long long bo = zb * sBb + zh * sBh_;
        const long long co = zb * sCb + zh * sCh_;
        Ahg += ao; if (ASPLIT) Alg += ao;
        Bhg += bo; Blg += bo;
        if (Cf)  Cf  += co;
        if (Chg) Chg += co;
        if (Clg) Clg += co;
    }
    int kmax = K;
    if (CK) { int lim = (bm + 1) * TM; kmax = lim < K ? lim : K; }

    extern __shared__ char sm[];
    const uint32_t sbase = smem_u32(sm);

    const int tid  = threadIdx.x;
    const int wid  = tid >> 5;
    const int lane = tid & 31;
    const int m0 = bm * TM, n0 = bn * TN;

    // warp tile: 64x32 (wm in {0,64}, wn in {0,32,64,96})
    const int wm = (wid >> 2) * 64;
    const int wn = (wid & 3) * 32;

    const int a_row = wm + (lane & 15);
    const int a_kb  = (lane >> 4) * 16;
    const int quad  = lane >> 3, qr = lane & 7;
    const int b_row = wn + ((quad >> 1) * 8) + qr;
    const int b_kb  = (quad & 1) * 16;

    float acc[4][4][4];
    #pragma unroll
    for (int i = 0; i < 4; ++i)
        #pragma unroll
        for (int n = 0; n < 4; ++n)
            #pragma unroll
            for (int r = 0; r < 4; ++r) acc[i][n][r] = 0.f;

    const int nch = kmax / TKC;   // >= 4 always

    auto load_stage = [&](int c, int st) {
        const uint32_t sb = sbase + (uint32_t)st * STB;
        const int k0 = c * TKC;
        #pragma unroll
        for (int it = 0; it < 2; ++it) {
            const int idx = tid + it * 256;      // 0..511
            const int row = idx >> 2, cc = idx & 3;
            const uint32_t so = SWZ64(row * 64 + cc * 16);
            const long long ga = (long long)(m0 + row) * lda + k0 + cc * 8;
            cp16(sb + so, Ahg + ga);
            if (ASPLIT) cp16(sb + OFF_AL + so, Alg + ga);
            const long long gb = (long long)(n0 + row) * ldb + k0 + cc * 8;
            cp16(sb + OFF_BH + so, Bhg + gb);
            cp16(sb + OFF_BL + so, Blg + gb);
        }
    };

    // prologue: 2 stages in flight (3 buffers)
    load_stage(0, 0); cp_commit();
    load_stage(1, 1); cp_commit();

    int st_c = 0;   // buffer holding chunk c
    int st_l = 2;   // buffer for chunk c+2
    for (int c = 0; c < nch; ++c) {
        cp_wait<1>();          // chunk c landed
        __syncthreads();       // publishes stage c, retires stage c-1's buffer

        if (c + 2 < nch) load_stage(c + 2, st_l);
        cp_commit();

        const uint32_t sA_h = sbase + (uint32_t)st_c * STB;
        const uint32_t sA_l = sA_h + OFF_AL;
        const uint32_t sB_h = sA_h + OFF_BH;
        const uint32_t sB_l = sA_h + OFF_BL;

        #pragma unroll
        for (int ks = 0; ks < 2; ++ks) {
            uint32_t ah[4][4], al[4][4];
            #pragma unroll
            for (int i = 0; i < 4; ++i) {
                const uint32_t o = SWZ64((a_row + i * 16) * 64 + ks * 32 + a_kb);
                LDSM4(ah[i], sA_h + o);
                if (ASPLIT) LDSM4(al[i], sA_l + o);
            }
            #pragma unroll
            for (int p = 0; p < 2; ++p) {          // 2 n-atoms per group
                const uint32_t o = SWZ64((b_row + p * 16) * 64 + ks * 32 + b_kb);
                uint32_t rh[4], rl[4];
                LDSM4(rh, sB_h + o);
                LDSM4(rl, sB_l + o);
                #pragma unroll
                for (int na = 0; na < 2; ++na) {
                    uint32_t bh2[2] = { rh[na * 2], rh[na * 2 + 1] };
                    uint32_t bl2[2] = { rl[na * 2], rl[na * 2 + 1] };
                    const int n = p * 2 + na;
                    #pragma unroll
                    for (int i = 0; i < 4; ++i) {
                        MMA16816(acc[i][n], ah[i], bh2);
                        MMA16816(acc[i][n], ah[i], bl2);
                        if (ASPLIT) MMA16816(acc[i][n], al[i], bh2);
                    }
                }
            }
        }
        st_c = (st_c == 2) ? 0 : st_c + 1;
        st_l = (st_l == 2) ? 0 : st_l + 1;
    }

    // ---- epilogue (registers only) ----
    const int gid = lane >> 2, l4 = lane & 3;
    #pragma unroll
    for (int i = 0; i < 4; ++i) {
        const int r0 = m0 + wm + i * 16 + gid;
        #pragma unroll
        for (int n = 0; n < 4; ++n) {
            const int col = n0 + wn + n * 8 + l4 * 2;
            if (EPI == 0) {
                #pragma unroll
                for (int half = 0; half < 2; ++half) {
                    const int rr = r0 + half * 8;
                    const float v0 = acc[i][n][half * 2 + 0];
                    const float v1 = acc[i][n][half * 2 + 1];
                    const __half h0 = __float2half_rn(v0);
                    const __half h1 = __float2half_rn(v1);
                    const __half l0 = __float2half_rn(v0 - __half2float(h0));
                    const __half l1 = __float2half_rn(v1 - __half2float(h1));
                    *(uint32_t*)(Chg + (long long)rr * ldc + col) = pkh(h0, h1);
                    *(uint32_t*)(Clg + (long long)rr * ldc + col) = pkh(l0, l1);
                }
            } else if (EPI == 3) {
                #pragma unroll
                for (int half = 0; half < 2; ++half) {
                    const int rr = r0 + half * 8;
                    const __half h0 = __float2half_rn(acc[i][n][half * 2 + 0]);
                    const __half h1 = __float2half_rn(acc[i][n][half * 2 + 1]);
                    *(uint32_t*)(Chg + (long long)rr * ldc + col) = pkh(h0, h1);
                }
            } else {
                #pragma unroll
                for (int half = 0; half < 2; ++half) {
                    const int rr = r0 + half * 8;
                    float2 v;
                    v.x = acc[i][n][half * 2 + 0];
                    v.y = acc[i][n][half * 2 + 1];
                    if (EPI == 1) { v.x *= scale; v.y *= scale; }
                    if (EPI == 2) { v.x += bias[col]; v.y += bias[col + 1]; }
                    *(float2*)(Cf + (long long)rr * ldc + col) = v;
                }
            }
        }
    }
}

// ---------------- split fp32 -> fp16 hi/lo (vectorized x4) ----------------
__global__ __launch_bounds__(256) void split_kernel(
    const float* __restrict__ in, __half* __restrict__ hi,
    __half* __restrict__ lo, int n4)
{
    const int i = blockIdx.x * 256 + threadIdx.x;
    if (i < n4) {
        const float4 v = ((const float4*)in)[i];
        const __half h0 = __float2half_rn(v.x), h1 = __float2half_rn(v.y);
        const __half h2 = __float2half_rn(v.z), h3 = __float2half_rn(v.w);
        const __half l0 = __float2half_rn(v.x - __half2float(h0));
        const __half l1 = __float2half_rn(v.y - __half2float(h1));
        const __half l2 = __float2half_rn(v.z - __half2float(h2));
        const __half l3 = __float2half_rn(v.w - __half2float(h3));
        uint2 hv; hv.x = pkh(h0, h1); hv.y = pkh(h2, h3);
        uint2 lv; lv.x = pkh(l0, l1); lv.y = pkh(l2, l3);
        ((uint2*)hi)[i] = hv;
        ((uint2*)lo)[i] = lv;
    }
}

// ---------------- tiled transpose of split V: [b, t, he] -> [b, he, t] ----------------
__global__ __launch_bounds__(256) void transpose_kernel(
    const __half* __restrict__ ih, const __half* __restrict__ il,
    __half* __restrict__ oh, __half* __restrict__ ol)
{
    __shared__ __half th[32][33], tl[32][33];
    const int b = blockIdx.z;
    const int n0 = blockIdx.x * 32, t0 = blockIdx.y * 32;
    const int tx = threadIdx.x, ty = threadIdx.y;
    #pragma unroll
    for (int j = ty; j < 32; j += 8) {
        const long long g = ((long long)b * Tq + t0 + j) * HE + n0 + tx;
        th[j][tx] = ih[g];
        tl[j][tx] = il[g];
    }
    __syncthreads();
    #pragma unroll
    for (int j = ty; j < 32; j += 8) {
        const long long g = ((long long)b * HE + n0 + j) * Tq + t0 + tx;
        oh[g] = th[tx][j];
        ol[g] = tl[tx][j];
    }
}

// ---------------- causal softmax: fp32 scores -> plain fp16 probs ----------------
__global__ __launch_bounds__(256) void softmax_kernel(
    const float* __restrict__ S, __half* __restrict__ Ph)
{
    const int z = blockIdx.y, q = blockIdx.x;
    const long long base = (long long)z * Tq * Tq + (long long)q * Tq;
    const float* row = S + base;
    __half* ph_ = Ph + base;
    const int len = q + 1;
    const int klim = ((q >> 7) + 1) << 7;   // PV reads only k < klim
    const int tid = threadIdx.x;

    __shared__ float rowbuf[Tq];
    __shared__ float red[256];

    float m = -1e30f;
    for (int k = tid; k < len; k += 256) {
        const float v = row[k];
        rowbuf[k] = v;
        m = fmaxf(m, v);
    }
    red[tid] = m; __syncthreads();
    for (int s = 128; s > 0; s >>= 1) {
        if (tid < s) red[tid] = fmaxf(red[tid], red[tid + s]);
        __syncthreads();
    }
    m = red[0]; __syncthreads();

    float sum = 0.f;
    for (int k = tid; k < len; k += 256) {
        const float e = expf(rowbuf[k] - m);
        rowbuf[k] = e;
        sum += e;
    }
    red[tid] = sum; __syncthreads();
    for (int s = 128; s > 0; s >>= 1) {
        if (tid < s) red[tid] += red[tid + s];
        __syncthreads();
    }
    const float inv = 1.0f / red[0]; __syncthreads();

    for (int k = tid; k < klim; k += 256) {
        const float p = (k < len) ? rowbuf[k] * inv : 0.0f;
        ph_[k] = __float2half_rn(p);
    }
}

// ---------------- host ----------------
extern "C" void kernel_launch(void* const* d_in, const int* in_sizes, int n_in,
                              void* d_out, int out_size)
{
    const float* x  = (const float*)d_in[0];
    const float* Wk = (const float*)d_in[1];
    const float* Wq = (const float*)d_in[2];
    const float* Wv = (const float*)d_in[3];
    const float* Wc = (const float*)d_in[4];
    const float* bc = (const float*)d_in[5];
    float* out = (float*)d_out;

    float* S;
    __half *Qh, *Ql, *Kh, *Kl, *Vh, *Vl, *Vth, *Vtl, *Oh, *Ph;
    __half *xh, *xl, *Wqh, *Wql, *Wkh, *Wkl, *Wvh, *Wvl, *Wch, *Wcl;
    cudaGetSymbolAddress((void**)&S,   g_S);
    cudaGetSymbolAddress((void**)&Qh,  g_Qh);  cudaGetSymbolAddress((void**)&Ql,  g_Ql);
    cudaGetSymbolAddress((void**)&Kh,  g_Kh);  cudaGetSymbolAddress((void**)&Kl,  g_Kl);
    cudaGetSymbolAddress((void**)&Vh,  g_Vh);  cudaGetSymbolAddress((void**)&Vl,  g_Vl);
    cudaGetSymbolAddress((void**)&Vth, g_Vth); cudaGetSymbolAddress((void**)&Vtl, g_Vtl);
    cudaGetSymbolAddress((void**)&Oh,  g_Oh);
    cudaGetSymbolAddress((void**)&Ph,  g_Ph);
    cudaGetSymbolAddress((void**)&xh,  g_xh);  cudaGetSymbolAddress((void**)&xl,  g_xl);
    cudaGetSymbolAddress((void**)&Wqh, g_Wqh); cudaGetSymbolAddress((void**)&Wql, g_Wql);
    cudaGetSymbolAddress((void**)&Wkh, g_Wkh); cudaGetSymbolAddress((void**)&Wkl, g_Wkl);
    cudaGetSymbolAddress((void**)&Wvh, g_Wvh); cudaGetSymbolAddress((void**)&Wvl, g_Wvl);
    cudaGetSymbolAddress((void**)&Wch, g_Wch); cudaGetSymbolAddress((void**)&Wcl, g_Wcl);

    const int SM_SPLIT  = 3 * 32768;   // 96 KB -> 2 CTAs/SM
    const int SM_SINGLE = 3 * 24576;   // 72 KB -> 2 CTAs/SM

    cudaFuncSetAttribute(tc_gemm<0, false, false, true >, cudaFuncAttributeMaxDynamicSharedMemorySize, SM_SPLIT);
    cudaFuncSetAttribute(tc_gemm<1, true,  false, true >, cudaFuncAttributeMaxDynamicSharedMemorySize, SM_SPLIT);
    cudaFuncSetAttribute(tc_gemm<3, false, true,  false>, cudaFuncAttributeMaxDynamicSharedMemorySize, SM_SINGLE);
    cudaFuncSetAttribute(tc_gemm<2, false, false, false>, cudaFuncAttributeMaxDynamicSharedMemorySize, SM_SINGLE);

    const dim3 blk(256);

    // 0) split inputs (vectorized x4)
    {
        const int n4 = (int)(NX / 4);
        const int g = (n4 + 255) / 256;
        split_kernel<<<g, 256>>>(x,  xh,  xl,  n4);
        split_kernel<<<g, 256>>>(Wq, Wqh, Wql, n4);
        split_kernel<<<g, 256>>>(Wk, Wkh, Wkl, n4);
        split_kernel<<<g, 256>>>(Wv, Wvh, Wvl, n4);
        split_kernel<<<g, 256>>>(Wc, Wch, Wcl, n4);
    }

    // 1) projections: [BT, HE] = x[BT, Eq] @ W[HE, Eq]^T (split outputs, 3-term)
    {
        dim3 grid(HE / TN, BT / TM, 1);
        tc_gemm<0, false, false, true><<<grid, blk, SM_SPLIT>>>(
            xh, xl, Eq, Wqh, Wql, Eq, nullptr, Qh, Ql, HE,
            Eq, 0.f, nullptr, 1, 0, 0, 0, 0, 0, 0);
        tc_gemm<0, false, false, true><<<grid, blk, SM_SPLIT>>>(
            xh, xl, Eq, Wkh, Wkl, Eq, nullptr, Kh, Kl, HE,
            Eq, 0.f, nullptr, 1, 0, 0, 0, 0, 0, 0);
        tc_gemm<0, false, false, true><<<grid, blk, SM_SPLIT>>>(
            xh, xl, Eq, Wvh, Wvl, Eq, nullptr, Vh, Vl, HE,
            Eq, 0.f, nullptr, 1, 0, 0, 0, 0, 0, 0);
    }

    // 2) transpose V -> [b, he, t] (K-major B for PV)
    {
        dim3 grid(HE / 32, Tq / 32, Bq), b2(32, 8);
        transpose_kernel<<<grid, b2>>>(Vh, Vl, Vth, Vtl);
    }

    // 3) scores: S = scale * Q K^T (causal tile skip, 3-term, fp32 out)
    {
        dim3 grid(Tq / TN, Tq / TM, Bq * Hq);
        tc_gemm<1, true, false, true><<<grid, blk, SM_SPLIT>>>(
            Qh, Ql, HE, Kh, Kl, HE, S, nullptr, nullptr, Tq,
            Eq, SCALE_F, nullptr, Hq,
            (long long)Tq * HE, (long long)Eq,
            (long long)Tq * HE, (long long)Eq,
            (long long)Hq * Tq * Tq, (long long)Tq * Tq);
    }

    // 4) softmax -> plain fp16 probs
    {
        dim3 grid(Tq, Bq * Hq);
        softmax_kernel<<<grid, 256>>>(S, Ph);
    }

    // 5) PV: O = P @ V (A single fp16, B split, causal K bound, fp16 out)
    {
        dim3 grid(Eq / TN, Tq / TM, Bq * Hq);
        tc_gemm<3, false, true, false><<<grid, blk, SM_SINGLE>>>(
            Ph, nullptr, Tq, Vth, Vtl, Tq, nullptr, Oh, nullptr, HE,
            Tq, 0.f, nullptr, Hq,
            (long long)Hq * Tq * Tq, (long long)Tq * Tq,
            (long long)HE * Tq, (long long)Eq * Tq,
            (long long)Tq * HE, (long long)Eq);
    }

    // 6) output projection: out = O @ Wc^T + bc (A single fp16, B split, fp32)
    {
        dim3 grid(Eq / TN, BT / TM, 1);
        tc_gemm<2, false, false, false><<<grid, blk, SM_SINGLE>>>(
            Oh, nullptr, HE, Wch, Wcl, HE, out, nullptr, nullptr, Eq,
            HE, 0.f, bc, 1, 0, 0, 0, 0, 0, 0);
    }
}